// round 1
// baseline (speedup 1.0000x reference)
#include <cuda_runtime.h>
#include <math.h>

#define TT 1024
#define BB 512
#define KK 128
#define GG 4   // batches per block

// ---- packed f32x2 helpers (sm_103a) ----
__device__ __forceinline__ unsigned long long pk2(float a, float b) {
    unsigned long long r;
    asm("mov.b64 %0, {%1,%2};" : "=l"(r) : "f"(a), "f"(b));
    return r;
}
__device__ __forceinline__ void fma2(unsigned long long& d, unsigned long long a, unsigned long long b) {
    asm("fma.rn.f32x2 %0, %1, %2, %0;" : "+l"(d) : "l"(a), "l"(b));
}
__device__ __forceinline__ void upk2(unsigned long long v, float& a, float& b) {
    asm("mov.b64 {%0,%1}, %2;" : "=f"(a), "=f"(b) : "l"(v));
}

__global__ void zero_out_kernel(float* out) {
    if (threadIdx.x == 0) out[0] = 0.0f;
}

__global__ void __launch_bounds__(128, 1) crf_kernel(
    const float* __restrict__ em,      // [T,B,K]
    const int*   __restrict__ tags,    // [T,B]
    const float* __restrict__ mask,    // [T,B]
    const float* __restrict__ startT,  // [K]
    const float* __restrict__ trans,   // [K,K]
    const float* __restrict__ endT,    // [K]
    float* __restrict__ out)
{
    __shared__ float  transS[KK * KK];   // raw transitions (for gold-path gather)
    __shared__ float4 pv[2][KK];         // ping-pong u-state: [buf][i] -> 4 batches
    __shared__ float  wred[4][2 * GG];   // warp partials (max / sums)

    const int j    = threadIdx.x;        // tag column this thread owns
    const int warp = j >> 5;
    const int lane = j & 31;
    const int b0   = blockIdx.x * GG;

    // stage raw transitions into smem
    for (int k = j; k < KK * KK; k += 128) transS[k] = trans[k];
    __syncthreads();

    // E column in registers: Ereg[i] = exp(trans[i][j])  (accurate expf, one-time)
    float Ereg[KK];
#pragma unroll
    for (int i = 0; i < KK; i++) Ereg[i] = expf(transS[i * KK + j]);

    const float sj = startT[j];

    float  u[GG];        // linear-domain state for column j, 4 batches
    double C[GG];        // log-scale offset per batch (exact bookkeeping)
    float  pathAcc[GG];  // sparse gold-path partial
    float  msum[GG];
    int    tgPrev[GG];

    // ---- t = 0 init: u = exp(start + em0), C = 0 ----
#pragma unroll
    for (int g = 0; g < GG; g++) {
        float e0 = em[(0 * BB + b0 + g) * KK + j];
        u[g] = expf(sj + e0);
        C[g] = 0.0;
        int   tg0 = tags[0 * BB + b0 + g];
        float m0  = mask[0 * BB + b0 + g];
        float pa = 0.0f;
        if (j == tg0) pa = sj + e0 * m0;  // start uncond + em0 * mask (matches reference)
        pathAcc[g] = pa;
        msum[g]    = m0;
        tgPrev[g]  = tg0;
    }
    pv[1][j] = make_float4(u[0], u[1], u[2], u[3]);  // step t=1 reads buf (t&1)=1
    __syncthreads();

    const unsigned pv_base = (unsigned)__cvta_generic_to_shared(&pv[0][0]);

    for (int t = 1; t < TT; t++) {
        const int r = t & 1;
        const int w = 1 - r;

        // issue this step's global loads up front; consumed after the matvec
        float eraw[GG]; int tg[GG]; float mv[GG];
#pragma unroll
        for (int g = 0; g < GG; g++) {
            eraw[g] = em[(t * BB + b0 + g) * KK + j];
            tg[g]   = tags[t * BB + b0 + g];
            mv[g]   = mask[t * BB + b0 + g];
        }

        // ---- matvec: S[g] = sum_i u_prev[g][i] * E[i][j] ----
        const unsigned base = pv_base + (unsigned)(r * (KK * 16));
        unsigned long long acc01 = 0ull, acc23 = 0ull;
#pragma unroll
        for (int i = 0; i < KK; i++) {
            unsigned long long p01, p23;
            asm volatile("ld.shared.v2.b64 {%0,%1}, [%2];"
                         : "=l"(p01), "=l"(p23)
                         : "r"(base + (unsigned)(i * 16)));
            unsigned long long e2 = pk2(Ereg[i], Ereg[i]);
            fma2(acc01, e2, p01);
            fma2(acc23, e2, p23);
        }

        float S[GG];
        upk2(acc01, S[0], S[1]);
        upk2(acc23, S[2], S[3]);

#pragma unroll
        for (int g = 0; g < GG; g++) {
            float un = __expf(eraw[g]) * S[g];
            u[g] = (mv[g] != 0.0f) ? un : u[g];   // masked step: state unchanged
            if (j == tg[g]) {
                pathAcc[g] += (eraw[g] + transS[tgPrev[g] * KK + j]) * mv[g];
            }
            msum[g]  += mv[g];
            tgPrev[g] = tg[g];
        }

        // ---- exact power-of-2 rescale every 4 steps ----
        if ((t & 3) == 0) {
            float wm[GG];
#pragma unroll
            for (int g = 0; g < GG; g++) {
                float v = u[g];
                for (int o = 16; o; o >>= 1) v = fmaxf(v, __shfl_xor_sync(0xffffffffu, v, o));
                wm[g] = v;
            }
            if (lane == 0) {
#pragma unroll
                for (int g = 0; g < GG; g++) wred[warp][g] = wm[g];
            }
            __syncthreads();
#pragma unroll
            for (int g = 0; g < GG; g++) {
                float m = fmaxf(fmaxf(wred[0][g], wred[1][g]),
                                fmaxf(wred[2][g], wred[3][g]));
                int e = ilogbf(m);
                float s = __int_as_float((unsigned)(127 - e) << 23);  // exact 2^-e
                u[g] *= s;
                C[g] += (double)e * 0.6931471805599453;
            }
        }

        pv[w][j] = make_float4(u[0], u[1], u[2], u[3]);
        __syncthreads();
    }

    // ---- finalize: logZ = C + log(sum_j u[j]*exp(end[j])), path += end[lastTag] ----
    const float ezj = expf(endT[j]);
#pragma unroll
    for (int g = 0; g < GG; g++) {
        float z = u[g] * ezj;
        float p = pathAcc[g];
        for (int o = 16; o; o >>= 1) {
            z += __shfl_xor_sync(0xffffffffu, z, o);
            p += __shfl_xor_sync(0xffffffffu, p, o);
        }
        if (lane == 0) { wred[warp][g] = z; wred[warp][GG + g] = p; }
    }
    __syncthreads();
    if (j < GG) {
        const int g = j;
        float zsum = wred[0][g] + wred[1][g] + wred[2][g] + wred[3][g];
        float psum = wred[0][GG + g] + wred[1][GG + g] + wred[2][GG + g] + wred[3][GG + g];
        int cnt = (int)(msum[g] + 0.5f);
        if (cnt < 1) cnt = 1;
        int lastTag = tags[(cnt - 1) * BB + b0 + g];
        double pathTot = (double)psum + (double)endT[lastTag];
        double logZ    = C[g] + log((double)zsum);
        atomicAdd(out, (float)(pathTot - logZ));
    }
}

extern "C" void kernel_launch(void* const* d_in, const int* in_sizes, int n_in,
                              void* d_out, int out_size) {
    const float* em     = (const float*)d_in[0];
    const int*   tags   = (const int*)  d_in[1];
    const float* mask   = (const float*)d_in[2];
    const float* startT = (const float*)d_in[3];
    const float* trans  = (const float*)d_in[4];
    const float* endT   = (const float*)d_in[5];
    float* out = (float*)d_out;

    zero_out_kernel<<<1, 32>>>(out);
    crf_kernel<<<BB / GG, KK>>>(em, tags, mask, startT, trans, endT, out);
}

// round 3
// speedup vs baseline: 1.2824x; 1.2824x over previous
#include <cuda_runtime.h>
#include <math.h>

#define TT 1024
#define BB 512
#define KK 128
#define GG 4   // batches per block

// ---- packed f32x2 helpers (sm_103a), all NON-volatile so ptxas can schedule ----
__device__ __forceinline__ unsigned long long pk2(float a, float b) {
    unsigned long long r;
    asm("mov.b64 %0, {%1,%2};" : "=l"(r) : "f"(a), "f"(b));
    return r;
}
__device__ __forceinline__ void fma2(unsigned long long& d, unsigned long long a, unsigned long long b) {
    asm("fma.rn.f32x2 %0, %1, %2, %0;" : "+l"(d) : "l"(a), "l"(b));
}
__device__ __forceinline__ void upk2(unsigned long long v, float& a, float& b) {
    asm("mov.b64 {%0,%1}, %2;" : "=f"(a), "=f"(b) : "l"(v));
}

__global__ void zero_out_kernel(float* out) {
    if (threadIdx.x == 0) out[0] = 0.0f;
}

// ---- gold-path score: trivially parallel gather-reduce, one block per batch ----
__global__ void __launch_bounds__(128) path_kernel(
    const float* __restrict__ em, const int* __restrict__ tags,
    const float* __restrict__ mask, const float* __restrict__ startT,
    const float* __restrict__ trans, const float* __restrict__ endT,
    float* __restrict__ out)
{
    __shared__ float sacc[4], smsum[4];
    const int b = blockIdx.x, tid = threadIdx.x, warp = tid >> 5, lane = tid & 31;
    float acc = 0.0f, msum = 0.0f;
    for (int t = tid; t < TT; t += 128) {
        int   tg = tags[t * BB + b];
        float m  = mask[t * BB + b];
        acc  += em[(t * BB + b) * KK + tg] * m;
        msum += m;
        if (t > 0) {
            int tp = tags[(t - 1) * BB + b];
            acc += trans[tp * KK + tg] * m;
        }
    }
    for (int o = 16; o; o >>= 1) {
        acc  += __shfl_xor_sync(0xffffffffu, acc, o);
        msum += __shfl_xor_sync(0xffffffffu, msum, o);
    }
    if (lane == 0) { sacc[warp] = acc; smsum[warp] = msum; }
    __syncthreads();
    if (tid == 0) {
        float a  = sacc[0] + sacc[1] + sacc[2] + sacc[3];
        float ms = smsum[0] + smsum[1] + smsum[2] + smsum[3];
        int cnt = (int)(ms + 0.5f); if (cnt < 1) cnt = 1;
        a += startT[tags[b]] + endT[tags[(cnt - 1) * BB + b]];
        atomicAdd(out, a);
    }
}

// ---- forward recurrence: scaled linear domain, packed-f32x2 matvec ----
__global__ void __launch_bounds__(128, 1) crf_fwd_kernel(
    const float* __restrict__ em,      // [T,B,K]
    const float* __restrict__ mask,    // [T,B]
    const float* __restrict__ startT,  // [K]
    const float* __restrict__ trans,   // [K,K]
    const float* __restrict__ endT,    // [K]
    float* __restrict__ out)
{
    __shared__ alignas(16) float pv[2][GG][KK];  // [buf][batch][i]
    __shared__ float wred[4][GG];

    const int j    = threadIdx.x;   // tag column owned by this thread
    const int warp = j >> 5;
    const int lane = j & 31;
    const int b0   = blockIdx.x * GG;

    // E column pre-packed over i: epk[m] = (exp(trans[2m][j]), exp(trans[2m+1][j]))
    unsigned long long epk[KK / 2];
#pragma unroll
    for (int m = 0; m < KK / 2; m++) {
        epk[m] = pk2(expf(trans[(2 * m) * KK + j]),
                     expf(trans[(2 * m + 1) * KK + j]));
    }

    float u[GG];
    int   Ce[GG];   // exact power-of-2 scale exponent
    const float sj = startT[j];
#pragma unroll
    for (int g = 0; g < GG; g++) {
        u[g]  = expf(sj + em[(b0 + g) * KK + j]);
        Ce[g] = 0;
        pv[1][g][j] = u[g];     // step t=1 reads buffer (t&1)=1
    }
    __syncthreads();

    for (int t = 1; t < TT; t++) {
        const int r = t & 1, w = r ^ 1;

        // this step's global loads (hoistable; consumed after the matvec)
        float eraw[GG], mv[GG];
#pragma unroll
        for (int g = 0; g < GG; g++) {
            eraw[g] = __ldg(&em[(t * BB + b0 + g) * KK + j]);
            mv[g]   = __ldg(&mask[t * BB + b0 + g]);
        }

        // matvec: S[g] = sum_i u_prev[g][i] * E[i][j]; 8 independent acc chains
        unsigned long long acc0[GG], acc1[GG];
#pragma unroll
        for (int g = 0; g < GG; g++) { acc0[g] = 0ull; acc1[g] = 0ull; }
#pragma unroll
        for (int k = 0; k < KK / 4; k++) {
#pragma unroll
            for (int g = 0; g < GG; g++) {
                const ulonglong2 q = *(const ulonglong2*)&pv[r][g][4 * k];  // LDS.128 broadcast
                fma2(acc0[g], epk[2 * k],     q.x);
                fma2(acc1[g], epk[2 * k + 1], q.y);
            }
        }

#pragma unroll
        for (int g = 0; g < GG; g++) {
            float a, b, c, d;
            upk2(acc0[g], a, b);
            upk2(acc1[g], c, d);
            float S  = (a + b) + (c + d);
            float un = __expf(eraw[g]) * S;
            u[g] = (mv[g] != 0.0f) ? un : u[g];
        }

        // exact power-of-2 rescale every 8 steps
        if ((t & 7) == 0) {
            float wm[GG];
#pragma unroll
            for (int g = 0; g < GG; g++) {
                float v = u[g];
                for (int o = 16; o; o >>= 1) v = fmaxf(v, __shfl_xor_sync(0xffffffffu, v, o));
                wm[g] = v;
            }
            if (lane == 0) {
#pragma unroll
                for (int g = 0; g < GG; g++) wred[warp][g] = wm[g];
            }
            __syncthreads();
#pragma unroll
            for (int g = 0; g < GG; g++) {
                float m = fmaxf(fmaxf(wred[0][g], wred[1][g]),
                                fmaxf(wred[2][g], wred[3][g]));
                int e   = ilogbf(m);
                float s = __int_as_float((unsigned)(127 - e) << 23);  // exact 2^-e
                u[g]  *= s;
                Ce[g] += e;
            }
        }

#pragma unroll
        for (int g = 0; g < GG; g++) pv[w][g][j] = u[g];
        __syncthreads();
    }

    // finalize: -logZ = -(Ce*ln2 + log(sum_j u[j]*exp(end[j])))
    const float ezj = expf(endT[j]);
#pragma unroll
    for (int g = 0; g < GG; g++) {
        float z = u[g] * ezj;
        for (int o = 16; o; o >>= 1) z += __shfl_xor_sync(0xffffffffu, z, o);
        if (lane == 0) wred[warp][g] = z;
    }
    __syncthreads();
    if (j < GG) {
        const int g = j;
        float zsum  = wred[0][g] + wred[1][g] + wred[2][g] + wred[3][g];
        double logZ = (double)Ce[g] * 0.6931471805599453 + log((double)zsum);
        atomicAdd(out, (float)(-logZ));
    }
}

extern "C" void kernel_launch(void* const* d_in, const int* in_sizes, int n_in,
                              void* d_out, int out_size) {
    const float* em     = (const float*)d_in[0];
    const int*   tags   = (const int*)  d_in[1];
    const float* mask   = (const float*)d_in[2];
    const float* startT = (const float*)d_in[3];
    const float* trans  = (const float*)d_in[4];
    const float* endT   = (const float*)d_in[5];
    float* out = (float*)d_out;

    zero_out_kernel<<<1, 32>>>(out);
    path_kernel<<<BB, 128>>>(em, tags, mask, startT, trans, endT, out);
    crf_fwd_kernel<<<BB / GG, KK>>>(em, mask, startT, trans, endT, out);
}

// round 4
// speedup vs baseline: 1.6528x; 1.2889x over previous
#include <cuda_runtime.h>
#include <math.h>

#define TT 1024
#define BB 512
#define KK 128
#define GG 2   // batches per block (occupancy 2 per SM)

// ---- packed f32x2 helpers (sm_103a), NON-volatile so ptxas can schedule ----
__device__ __forceinline__ unsigned long long pk2(float a, float b) {
    unsigned long long r;
    asm("mov.b64 %0, {%1,%2};" : "=l"(r) : "f"(a), "f"(b));
    return r;
}
__device__ __forceinline__ void fma2(unsigned long long& d, unsigned long long a, unsigned long long b) {
    asm("fma.rn.f32x2 %0, %1, %2, %0;" : "+l"(d) : "l"(a), "l"(b));
}
__device__ __forceinline__ void upk2(unsigned long long v, float& a, float& b) {
    asm("mov.b64 {%0,%1}, %2;" : "=f"(a), "=f"(b) : "l"(v));
}

__device__ float g_negLogZ[BB];   // scratch: -logZ per batch (written by fwd, read by path)

// ---- forward recurrence: scaled linear domain, packed-f32x2 matvec ----
// grid = BB/GG = 256 blocks, 128 threads, 2 CTAs per SM.
__global__ void __launch_bounds__(128, 2) crf_fwd_kernel(
    const float* __restrict__ em,      // [T,B,K]
    const float* __restrict__ mask,    // [T,B]
    const float* __restrict__ startT,  // [K]
    const float* __restrict__ trans,   // [K,K]
    const float* __restrict__ endT,    // [K]
    float* __restrict__ out)
{
    __shared__ alignas(16) float pv[2][GG][KK];  // [buf][batch][i]
    __shared__ float wred[4][GG];

    const int j    = threadIdx.x;   // tag column owned by this thread
    const int warp = j >> 5;
    const int lane = j & 31;
    const int b0   = blockIdx.x * GG;

    if (blockIdx.x == 0 && j == 0) out[0] = 0.0f;  // zero for launch-2 atomics

    // E column pre-packed over i: epk[m] = (exp(trans[2m][j]), exp(trans[2m+1][j]))
    unsigned long long epk[KK / 2];
#pragma unroll
    for (int m = 0; m < KK / 2; m++) {
        epk[m] = pk2(__expf(trans[(2 * m) * KK + j]),
                     __expf(trans[(2 * m + 1) * KK + j]));
    }

    float u[GG];
    int   Ce[GG];   // exact power-of-2 scale exponent
    const float sj = startT[j];
#pragma unroll
    for (int g = 0; g < GG; g++) {
        u[g]  = __expf(sj + em[(b0 + g) * KK + j]);
        Ce[g] = 0;
        pv[1][g][j] = u[g];     // step t=1 reads buffer (t&1)=1
    }
    __syncthreads();

    for (int t = 1; t < TT; t++) {
        const int r = t & 1, w = r ^ 1;

        // this step's global loads (consumed only after the matvec)
        float eraw[GG], mv[GG];
#pragma unroll
        for (int g = 0; g < GG; g++) {
            eraw[g] = __ldg(&em[(t * BB + b0 + g) * KK + j]);
            mv[g]   = __ldg(&mask[t * BB + b0 + g]);
        }

        // matvec: S[g] = sum_i u_prev[g][i] * E[i][j]; 4 independent acc chains
        unsigned long long acc0[GG], acc1[GG];
#pragma unroll
        for (int g = 0; g < GG; g++) { acc0[g] = 0ull; acc1[g] = 0ull; }
#pragma unroll
        for (int k = 0; k < KK / 4; k++) {
#pragma unroll
            for (int g = 0; g < GG; g++) {
                const ulonglong2 q = *(const ulonglong2*)&pv[r][g][4 * k];  // LDS.128 broadcast
                fma2(acc0[g], epk[2 * k],     q.x);
                fma2(acc1[g], epk[2 * k + 1], q.y);
            }
        }

#pragma unroll
        for (int g = 0; g < GG; g++) {
            float a, b, c, d;
            upk2(acc0[g], a, b);
            upk2(acc1[g], c, d);
            float S  = (a + b) + (c + d);
            float un = __expf(eraw[g]) * S;
            u[g] = (mv[g] != 0.0f) ? un : u[g];
        }

        // exact power-of-2 rescale every 8 steps (worst-case growth ~2^15/step)
        if ((t & 7) == 0) {
            float wm[GG];
#pragma unroll
            for (int g = 0; g < GG; g++) {
                float v = u[g];
                for (int o = 16; o; o >>= 1) v = fmaxf(v, __shfl_xor_sync(0xffffffffu, v, o));
                wm[g] = v;
            }
            if (lane == 0) {
#pragma unroll
                for (int g = 0; g < GG; g++) wred[warp][g] = wm[g];
            }
            __syncthreads();
#pragma unroll
            for (int g = 0; g < GG; g++) {
                float m = fmaxf(fmaxf(wred[0][g], wred[1][g]),
                                fmaxf(wred[2][g], wred[3][g]));
                int e   = ilogbf(m);
                float s = __int_as_float((unsigned)(127 - e) << 23);  // exact 2^-e
                u[g]  *= s;
                Ce[g] += e;
            }
        }

#pragma unroll
        for (int g = 0; g < GG; g++) pv[w][g][j] = u[g];
        __syncthreads();
    }

    // finalize: -logZ[b] = -(Ce*ln2 + log(sum_j u[j]*exp(end[j])))
    const float ezj = __expf(endT[j]);
#pragma unroll
    for (int g = 0; g < GG; g++) {
        float z = u[g] * ezj;
        for (int o = 16; o; o >>= 1) z += __shfl_xor_sync(0xffffffffu, z, o);
        if (lane == 0) wred[warp][g] = z;
    }
    __syncthreads();
    if (j < GG) {
        const int g = j;
        float zsum  = wred[0][g] + wred[1][g] + wred[2][g] + wred[3][g];
        double logZ = (double)Ce[g] * 0.6931471805599453 + log((double)zsum);
        g_negLogZ[b0 + g] = (float)(-logZ);
    }
}

// ---- gold-path score + final combine: one block per batch ----
__global__ void __launch_bounds__(128) path_kernel(
    const float* __restrict__ em, const int* __restrict__ tags,
    const float* __restrict__ mask, const float* __restrict__ startT,
    const float* __restrict__ trans, const float* __restrict__ endT,
    float* __restrict__ out)
{
    __shared__ float sacc[4], smsum[4];
    const int b = blockIdx.x, tid = threadIdx.x, warp = tid >> 5, lane = tid & 31;
    float acc = 0.0f, msum = 0.0f;
    for (int t = tid; t < TT; t += 128) {
        int   tg = tags[t * BB + b];
        float m  = mask[t * BB + b];
        acc  += em[(t * BB + b) * KK + tg] * m;
        msum += m;
        if (t > 0) {
            int tp = tags[(t - 1) * BB + b];
            acc += trans[tp * KK + tg] * m;
        }
    }
    for (int o = 16; o; o >>= 1) {
        acc  += __shfl_xor_sync(0xffffffffu, acc, o);
        msum += __shfl_xor_sync(0xffffffffu, msum, o);
    }
    if (lane == 0) { sacc[warp] = acc; smsum[warp] = msum; }
    __syncthreads();
    if (tid == 0) {
        float a  = sacc[0] + sacc[1] + sacc[2] + sacc[3];
        float ms = smsum[0] + smsum[1] + smsum[2] + smsum[3];
        int cnt = (int)(ms + 0.5f); if (cnt < 1) cnt = 1;
        a += startT[tags[b]] + endT[tags[(cnt - 1) * BB + b]];
        atomicAdd(out, a + g_negLogZ[b]);
    }
}

extern "C" void kernel_launch(void* const* d_in, const int* in_sizes, int n_in,
                              void* d_out, int out_size) {
    const float* em     = (const float*)d_in[0];
    const int*   tags   = (const int*)  d_in[1];
    const float* mask   = (const float*)d_in[2];
    const float* startT = (const float*)d_in[3];
    const float* trans  = (const float*)d_in[4];
    const float* endT   = (const float*)d_in[5];
    float* out = (float*)d_out;

    crf_fwd_kernel<<<BB / GG, KK>>>(em, mask, startT, trans, endT, out);
    path_kernel<<<BB, 128>>>(em, tags, mask, startT, trans, endT, out);
}